// round 14
// baseline (speedup 1.0000x reference)
#include <cuda_runtime.h>
#include <cstddef>
#include <cstdint>

// Problem constants
#define BATCH 2
#define SEQ   2048
#define DMODEL 1024
#define NHEADS 16
#define DHEAD 64
#define MROWS (BATCH*SEQ)        // 4096

// ---------------- scratch (no allocation allowed) ----------------
// g_q: [B,H,S,Dh] Dh 8-group interleaved (tf32)
// g_k: [B,H,S,Dh] Dh 8-group interleaved AND S-rows 8-group interleaved (tf32)
// g_v: [B,H,Dh,S] S 8-group interleaved (tf32)
// g_ao: [M, DMODEL] k-columns 16-group interleaved, tf32 (O-GEMM A-side)
__device__ float g_q[BATCH*NHEADS*SEQ*DHEAD];
__device__ float g_k[BATCH*NHEADS*SEQ*DHEAD];
__device__ float g_v[BATCH*NHEADS*SEQ*DHEAD];
__device__ float g_ao[MROWS*DMODEL];
// 16-group k-permuted + tf32-rounded copies of inputs
__device__ float g_rx[3][MROWS*DMODEL];         // query/key_/value
__device__ float g_rw[4][DMODEL*DMODEL];        // Wq/Wk/Wv/Wo

// ---------------- helpers ----------------
__device__ __forceinline__ float cvt_tf32f(float x) {
    unsigned u;
    asm("cvt.rna.tf32.f32 %0, %1;" : "=r"(u) : "f"(x));
    return __uint_as_float(u);
}

__device__ __forceinline__ float ex2f(float x) {
    float y;
    asm("ex2.approx.ftz.f32 %0, %1;" : "=f"(y) : "f"(x));
    return y;
}

// 8-group interleave (attn K/Q/V fragment layout): old o -> new position
__device__ __forceinline__ int perm8(int o) {
    return (o < 4) ? (2 * o) : (2 * o - 7);
}

// 16-group interleave (GEMM k-dim): new[t*4+j] = old[t+4j]; old o -> new pos
__device__ __forceinline__ int perm16(int o) {
    return (o & 3) * 4 + (o >> 2);
}

__device__ __forceinline__ void mma_tf32(float* c, const unsigned* a, const unsigned* b) {
    asm volatile(
        "mma.sync.aligned.m16n8k8.row.col.f32.tf32.tf32.f32 "
        "{%0,%1,%2,%3}, {%4,%5,%6,%7}, {%8,%9}, {%0,%1,%2,%3};"
        : "+f"(c[0]), "+f"(c[1]), "+f"(c[2]), "+f"(c[3])
        : "r"(a[0]), "r"(a[1]), "r"(a[2]), "r"(a[3]),
          "r"(b[0]), "r"(b[1]));
}

__device__ __forceinline__ uint32_t smem_u32(const void* p) {
    uint32_t a;
    asm("{ .reg .u64 t; cvta.to.shared.u64 t, %1; cvt.u32.u64 %0, t; }"
        : "=r"(a) : "l"(p));
    return a;
}

__device__ __forceinline__ void cpa16(uint32_t dst, const void* src) {
    asm volatile("cp.async.cg.shared.global [%0], [%1], 16;"
                 :: "r"(dst), "l"(src) : "memory");
}
#define CPA_COMMIT() asm volatile("cp.async.commit_group;" ::: "memory")
#define CPA_WAIT1()  asm volatile("cp.async.wait_group 1;" ::: "memory")
#define CPA_WAIT0()  asm volatile("cp.async.wait_group 0;" ::: "memory")

// ---------------- pre-pass: k-column 16-group interleave + tf32 round ------
// new[g*16 + (o&3)*4 + (o>>2)] = tf32(old[g*16 + o])
struct PArgs {
    const float* in[7];
    float* out[7];
    int n16[7];       // number of 16-groups
};

__global__ __launch_bounds__(256) void permute_round(PArgs pa)
{
    const int z = blockIdx.y;
    const int i = blockIdx.x * 256 + threadIdx.x;
    if (i >= pa.n16[z]) return;
    const float4* src = (const float4*)pa.in[z] + 4 * (size_t)i;
    float4 v0 = src[0], v1 = src[1], v2 = src[2], v3 = src[3];
    // old[0..15] = {v0.xyzw, v1.xyzw, v2.xyzw, v3.xyzw}
    float4 o0, o1, o2, o3;
    o0.x = cvt_tf32f(v0.x);  // old0
    o0.y = cvt_tf32f(v1.x);  // old4
    o0.z = cvt_tf32f(v2.x);  // old8
    o0.w = cvt_tf32f(v3.x);  // old12
    o1.x = cvt_tf32f(v0.y);  // old1
    o1.y = cvt_tf32f(v1.y);  // old5
    o1.z = cvt_tf32f(v2.y);  // old9
    o1.w = cvt_tf32f(v3.y);  // old13
    o2.x = cvt_tf32f(v0.z);  // old2
    o2.y = cvt_tf32f(v1.z);  // old6
    o2.z = cvt_tf32f(v2.z);  // old10
    o2.w = cvt_tf32f(v3.z);  // old14
    o3.x = cvt_tf32f(v0.w);  // old3
    o3.y = cvt_tf32f(v1.w);  // old7
    o3.z = cvt_tf32f(v2.w);  // old11
    o3.w = cvt_tf32f(v3.w);  // old15
    float4* dst = (float4*)pa.out[z] + 4 * (size_t)i;
    dst[0] = o0; dst[1] = o1; dst[2] = o2; dst[3] = o3;
}

// ---------------- GEMM (tf32 mma, LDS.128 dual-kstep frags) ----------------
// Inputs 16-group k-permuted + tf32-rounded. CTA 128x128x32, 128 threads,
// warp tile 64x64. 2-stage cp.async, 1 sync/iter.
// Per warp per 16-group: 16 LDS.128 -> fragments for 2 ksteps -> 64 MMA.
// mode 0: plain [M,N] fp32 (O proj); mode 1: Q layout; mode 2: V layout;
// mode 3: K layout (dh + s-row 8-group interleave).
#define GP 48
#define G_STAGE 12288                   // floats: A 128*48 + B 128*48
#define G_BOFF  6144
#define G_SMEM_FLOATS (2 * G_STAGE)     // 98304 bytes

struct GArgs {
    const float* X[3];
    const float* W[3];
    const float* bias[3];
    float*       Y[3];
    int mode[3];
};

__global__ __launch_bounds__(128) void gemm_tf32(GArgs ga)
{
    extern __shared__ float sg[];
    const uint32_t smb = smem_u32(sg);

    const int z = blockIdx.z;
    const float* __restrict__ X    = ga.X[z];
    const float* __restrict__ W    = ga.W[z];
    const float* __restrict__ bias = ga.bias[z];
    float* __restrict__       Y    = ga.Y[z];
    const int mode = ga.mode[z];

    const int t    = threadIdx.x;
    const int lane = t & 31;
    const int wid  = t >> 5;
    const int gid  = lane >> 2;
    const int tg   = lane & 3;

    const int bm = blockIdx.y * 128;
    const int bn = blockIdx.x * 128;
    const int m_base = (wid >> 1) * 64;
    const int n_base = (wid & 1) * 64;

    float acc[4][8][4];
    #pragma unroll
    for (int mt = 0; mt < 4; mt++)
        #pragma unroll
        for (int nt = 0; nt < 8; nt++)
            #pragma unroll
            for (int i = 0; i < 4; i++) acc[mt][nt][i] = 0.f;

    {
        const float* xs = X + (size_t)bm * DMODEL;
        const float* ws = W + (size_t)bn * DMODEL;
        #pragma unroll
        for (int l = 0; l < 8; l++) {
            int id = t + 128 * l;
            int r  = id >> 3, q = id & 7;
            cpa16(smb + (uint32_t)(r * GP + q * 4) * 4,
                  xs + (size_t)r * DMODEL + q * 4);
            cpa16(smb + (uint32_t)(G_BOFF + r * GP + q * 4) * 4,
                  ws + (size_t)r * DMODEL + q * 4);
        }
        CPA_COMMIT();
    }

    for (int c = 0; c < 32; c++) {
        CPA_WAIT0();
        __syncthreads();

        if (c + 1 < 32) {
            const int naof = ((c + 1) & 1) * G_STAGE;
            const int k0   = (c + 1) * 32;
            const float* xs = X + (size_t)bm * DMODEL + k0;
            const float* ws = W + (size_t)bn * DMODEL + k0;
            #pragma unroll
            for (int l = 0; l < 8; l++) {
                int id = t + 128 * l;
                int r  = id >> 3, q = id & 7;
                cpa16(smb + (uint32_t)(naof + r * GP + q * 4) * 4,
                      xs + (size_t)r * DMODEL + q * 4);
                cpa16(smb + (uint32_t)(naof + G_BOFF + r * GP + q * 4) * 4,
                      ws + (size_t)r * DMODEL + q * 4);
            }
            CPA_COMMIT();
        }

        const float* As = sg + (c & 1) * G_STAGE;
        const float* Bs = As + G_BOFF;
        #pragma unroll
        for (int g = 0; g < 2; g++) {         // two 16-groups per chunk
            const int cb = g * 16 + 4 * tg;
            float4 af0[4], af1[4];            // per mt: rows gid, gid+8
            #pragma unroll
            for (int mt = 0; mt < 4; mt++) {
                int m = m_base + mt * 16;
                af0[mt] = *(const float4*)&As[(m + gid    ) * GP + cb];
                af1[mt] = *(const float4*)&As[(m + gid + 8) * GP + cb];
            }
            float4 bf[8];
            #pragma unroll
            for (int nt = 0; nt < 8; nt++) {
                int n = n_base + nt * 8;
                bf[nt] = *(const float4*)&Bs[(n + gid) * GP + cb];
            }
            // kstep 0 of group: a = {x, x', y, y'}, b = {x, y}
            #pragma unroll
            for (int mt = 0; mt < 4; mt++) {
                unsigned a[4] = { __float_as_uint(af0[mt].x), __float_as_uint(af1[mt].x),
                                  __float_as_uint(af0[mt].y), __float_as_uint(af1[mt].y) };
                #pragma unroll
                for (int nt = 0; nt < 8; nt++) {
                    unsigned b2[2] = { __float_as_uint(bf[nt].x), __float_as_uint(bf[nt].y) };
                    mma_tf32(acc[mt][nt], a, b2);
                }
            }
            // kstep 1 of group: a = {z, z', w, w'}, b = {z, w}
            #pragma unroll
            for (int mt = 0; mt < 4; mt++) {
                unsigned a[4] = { __float_as_uint(af0[mt].z), __float_as_uint(af1[mt].z),
                                  __float_as_uint(af0[mt].w), __float_as_uint(af1[mt].w) };
                #pragma unroll
                for (int nt = 0; nt < 8; nt++) {
                    unsigned b2[2] = { __float_as_uint(bf[nt].z), __float_as_uint(bf[nt].w) };
                    mma_tf32(acc[mt][nt], a, b2);
                }
            }
        }
    }

    // epilogue
    #pragma unroll
    for (int nt = 0; nt < 8; nt++) {
        int c0 = bn + n_base + nt * 8 + tg * 2;
        float b0 = bias[c0], b1 = bias[c0 + 1];
        #pragma unroll
        for (int mt = 0; mt < 4; mt++) {
            int r0 = bm + m_base + mt * 16 + gid;
            #pragma unroll
            for (int half = 0; half < 2; half++) {
                int m = r0 + half * 8;
                float v0 = acc[mt][nt][half * 2 + 0] + b0;
                float v1 = acc[mt][nt][half * 2 + 1] + b1;
                if (mode == 0) {
                    Y[(size_t)m * DMODEL + c0]     = v0;
                    Y[(size_t)m * DMODEL + c0 + 1] = v1;
                } else if (mode == 1 || mode == 3) {
                    int b_ = m >> 11;
                    int s  = m & (SEQ - 1);
                    if (mode == 3) s = (s & ~7) + perm8(s & 7);   // K: row perm
                    int h  = c0 >> 6;
                    int dh = c0 & (DHEAD - 1);
                    int g8 = dh & ~7, o = dh & 7;
                    size_t base = (((size_t)(b_ * NHEADS + h)) * SEQ + s) * DHEAD + g8;
                    Y[base + perm8(o)]     = cvt_tf32f(v0);
                    Y[base + perm8(o + 1)] = cvt_tf32f(v1);
                } else {
                    int b_ = m >> 11;
                    int s  = m & (SEQ - 1);
                    int h  = c0 >> 6;
                    int dh = c0 & (DHEAD - 1);
                    int sp = (s & ~7) + perm8(s & 7);
                    size_t base = (((size_t)(b_ * NHEADS + h)) * DHEAD + dh) * SEQ + sp;
                    Y[base]       = cvt_tf32f(v0);
                    Y[base + SEQ] = cvt_tf32f(v1);
                }
            }
        }
    }
}

// ---------------- attention: register flash, shuffle-free PV ---------------
#define KP 72
#define VP 72
#define A_STAGE 9216
#define A_SMEM_FLOATS (3 * A_STAGE)     // 110592 bytes

#define LOG2E 1.44269504088896340736f

__global__ __launch_bounds__(256) void attn_kernel(
    const float* __restrict__ Q, const float* __restrict__ K,
    const float* __restrict__ V, float* __restrict__ O)
{
    extern __shared__ float sm[];
    const uint32_t smb = smem_u32(sm);

    const int t    = threadIdx.x;
    const int lane = t & 31;
    const int wid  = t >> 5;
    const int gid  = lane >> 2;
    const int tg   = lane & 3;

    const int b  = blockIdx.z, h = blockIdx.y;
    const int q0 = blockIdx.x << 7;
    const size_t head_base = ((size_t)(b * NHEADS + h)) * SEQ * DHEAD;

    // ---- stage Q (scaled 0.125*log2e, tf32) into smem [128][72] ----
    {
        float (*Qs)[KP] = (float (*)[KP])sm;
        const float qs = 0.125f * LOG2E;
        #pragma unroll
        for (int l = 0; l < 8; l++) {
            int id = t + 256 * l;
            int r  = id >> 4;
            int d4 = (id & 15) << 2;
            float4 v = *(const float4*)&Q[head_base + (size_t)(q0 + r) * DHEAD + d4];
            Qs[r][d4+0] = cvt_tf32f(v.x * qs);
            Qs[r][d4+1] = cvt_tf32f(v.y * qs);
            Qs[r][d4+2] = cvt_tf32f(v.z * qs);
            Qs[r][d4+3] = cvt_tf32f(v.w * qs);
        }
    }
    __syncthreads();

    unsigned qf[8][4];
    {
        float (*Qs)[KP] = (float (*)[KP])sm;
        const int wrow = wid * 16;
        #pragma unroll
        for (int ks = 0; ks < 8; ks++) {
            const int kb = ks * 8;
            float2 qa = *(const float2*)&Qs[wrow + gid    ][kb + 2 * tg];
            float2 qb = *(const float2*)&Qs[wrow + gid + 8][kb + 2 * tg];
            qf[ks][0] = __float_as_uint(qa.x);
            qf[ks][1] = __float_as_uint(qb.x);
            qf[ks][2] = __float_as_uint(qa.y);
            qf[ks][3] = __float_as_uint(qb.y);
        }
    }
    __syncthreads();

    // ---- prologue: prefetch KV tiles 0,1 ----
    #pragma unroll
    for (int p = 0; p < 2; p++) {
        const int koff = p * A_STAGE;
        const int voff = p * A_STAGE + 4608;
        #pragma unroll
        for (int l = 0; l < 4; l++) {
            int id = t + 256 * l;
            int r  = id >> 4;
            int c4 = (id & 15) << 2;
            cpa16(smb + (uint32_t)(koff + r * KP + c4) * 4,
                  K + head_base + (size_t)(p * 64 + r) * DHEAD + c4);
            cpa16(smb + (uint32_t)(voff + r * VP + c4) * 4,
                  V + head_base + (size_t)r * SEQ + p * 64 + c4);
        }
        CPA_COMMIT();
    }

    float oacc[8][4];
    #pragma unroll
    for (int nt = 0; nt < 8; nt++)
        #pragma unroll
        for (int i = 0; i < 4; i++) oacc[nt][i] = 0.f;
    float m0 = -1e30f, m1 = -1e30f, l0 = 0.f, l1 = 0.f;

    const int NIT = SEQ / 64;   // 32
    for (int it = 0; it < NIT; it++) {
        if (it + 1 < NIT) { CPA_WAIT1(); } else { CPA_WAIT0(); }
        __syncthreads();

        if (it + 2 < NIT) {
            const int ns = (it + 2) % 3;
            const int nk = ns * A_STAGE;
            const int nv = ns * A_STAGE + 4608;
            #pragma unroll
            for (int l = 0; l < 4; l++) {
                int id = t + 256 * l;
                int r  = id >> 4;
                int c4 = (id & 15) << 2;
                cpa16(smb + (uint32_t)(nk + r * KP + c4) * 4,
                      K + head_base + (size_t)((it + 2) * 64 + r) * DHEAD + c4);
                cpa16(smb + (uint32_t)(nv + r * VP + c4) * 4,
                      V + head_base + (size_t)r * SEQ + (it + 2) * 64 + c4);
            }
            CPA_COMMIT();
        }

        const int stage = it % 3;
        const float* Ks = sm + stage * A_STAGE;
        const float* Vs = sm + stage * A_STAGE + 4608;

        // ---- S2 = (Q*0.125*log2e) K^T (K s-rows permuted: c-frag = kv {tg,tg+4}) ----
        float sacc[8][4];
        #pragma unroll
        for (int nt = 0; nt < 8; nt++)
            #pragma unroll
            for (int i = 0; i < 4; i++) sacc[nt][i] = 0.f;

        #pragma unroll
        for (int ks = 0; ks < 8; ks++) {
            const int kb = ks * 8;
            unsigned bfr[8][2];
            #pragma unroll
            for (int nt = 0; nt < 8; nt++) {
                float2 kk = *(const float2*)&Ks[(nt * 8 + gid) * KP + kb + 2 * tg];
                bfr[nt][0] = __float_as_uint(kk.x);
                bfr[nt][1] = __float_as_uint(kk.y);
            }
            #pragma unroll
            for (int nt = 0; nt < 8; nt++)
                mma_tf32(sacc[nt], qf[ks], bfr[nt]);
        }

        // ---- online softmax, base-2, single-op EX2 ----
        float mx0 = -1e30f, mx1 = -1e30f;
        #pragma unroll
        for (int nt = 0; nt < 8; nt++) {
            mx0 = fmaxf(mx0, fmaxf(sacc[nt][0], sacc[nt][1]));
            mx1 = fmaxf(mx1, fmaxf(sacc[nt][2], sacc[nt][3]));
        }
        mx0 = fmaxf(mx0, __shfl_xor_sync(0xffffffffu, mx0, 1));
        mx0 = fmaxf(mx0, __shfl_xor_sync(0xffffffffu, mx0, 2));
        mx1 = fmaxf(mx1, __shfl_xor_sync(0xffffffffu, mx1, 1));
        mx1 = fmaxf(mx1, __shfl_xor_sync(0xffffffffu, mx1, 2));

        float m0n = fmaxf(m0, mx0), m1n = fmaxf(m1, mx1);
        float sc0 = ex2f(m0 - m0n), sc1 = ex2f(m1 - m1n);
        m0 = m0n; m1 = m1n;

        float s0 = 0.f, s1 = 0.f;
        #pragma unroll
        for (int nt = 0; nt < 8; nt++) {
            sacc[nt][0] = ex2f(sacc[nt][0] - m0); s0 += sacc[nt][0];
            sacc[nt][1] = ex2f(sacc[nt][1] - m0); s0 += sacc[nt][1];
            sacc[nt][2] = ex2f(sacc[nt][2] - m1); s1 += sacc[nt][2];
            sacc[nt][3] = ex2f(sacc[nt][3] - m1); s1 += sacc[nt][3];
        }
        s0 += __shfl_xor_sync(0xffffffffu, s0, 1);
        s0 += __shfl_xor_sync(0xffffffffu, s0, 2);
        s1 += __shfl_xor_sync(0xffffffffu, s1, 1);
        s1 += __shfl_xor_sync(0xffffffffu, s1, 2);
        l0 = l0 * sc0 + s0;
        l1 = l1 * sc1 + s1;

        #pragma unroll
        for (int nt = 0; nt < 8; nt++) {
            oacc[nt][0] *= sc0; oacc[nt][1] *= sc0;
            oacc[nt][2] *= sc1; oacc[nt][3] *= sc1;
        }

        // ---- PV: a-frags are direct register renames of sacc ----
        #pragma unroll
        for (int ks = 0; ks < 8; ks++) {
            unsigned a[4];
            a[0] = __float_as_uint(sacc[ks][0]);
            a[1] = __float_as_uint(sacc[ks][2]);
            a[2] = __float_as_uint(sacc[ks][1]);
            a[3] = __float_as_uint(sacc[ks][3]);

            const int kb = ks * 8;
            #pragma unroll
            for (int nt = 0; nt < 8; nt++) {
                float2 vv = *(const float2*)&Vs[(nt * 8 + gid) * VP + kb + 2 * tg];
                unsigned b2[2];
                b2[0] = __float_as_uint(vv.x);
                b2[1] = __float_as_uint(vv.y);
                mma_tf32(oacc[nt], a, b2);
            }
        }
    }

    // ---- epilogue: normalize, write 16-group-interleaved rounded [B,S,D] ----
    {
        float il0 = 1.0f / l0, il1 = 1.0f / l1;
        int r0 = q0 + wid * 16 + gid;
        int r1 = r0 + 8;
        #pragma unroll
        for (int nt = 0; nt < 8; nt++) {
            int C0 = h * DHEAD + nt * 8 + tg * 2;      // logical d-col
            int C1 = C0 + 1;
            int np0 = (C0 & ~15) + perm16(C0 & 15);
            int np1 = (C1 & ~15) + perm16(C1 & 15);
            size_t base0 = ((size_t)(b * SEQ + r0)) * DMODEL;
            size_t base1 = ((size_t)(b * SEQ + r1)) * DMODEL;
            O[base0 + np0] = cvt_tf32f(oacc[nt][0] * il0);
            O[base0 + np1] = cvt_tf32f(oacc[nt][1] * il0);
            O[base1 + np0] = cvt_tf32f(oacc[nt][2] * il1);
            O[base1 + np1] = cvt_tf32f(oacc[nt][3] * il1);
        }
    }
}

extern "C" void kernel_launch(void* const* d_in, const int* in_sizes, int n_in,
                              void* d_out, int out_size)
{
    const float* query = (const float*)d_in[0];
    const float* key_  = (const float*)d_in[1];
    const float* value = (const float*)d_in[2];
    const float* Wq = (const float*)d_in[3];
    const float* bq = (const float*)d_in[4];
    const float* Wk = (const float*)d_in[5];
    const float* bk = (const float*)d_in[6];
    const float* Wv = (const float*)d_in[7];
    const float* bv = (const float*)d_in[8];
    const float* Wo = (const float*)d_in[9];
    const float* bo = (const float*)d_in[10];

    float *qptr, *kptr, *vptr, *aoptr, *rxptr, *rwptr;
    cudaGetSymbolAddress((void**)&qptr,  g_q);
    cudaGetSymbolAddress((void**)&kptr,  g_k);
    cudaGetSymbolAddress((void**)&vptr,  g_v);
    cudaGetSymbolAddress((void**)&aoptr, g_ao);
    cudaGetSymbolAddress((void**)&rxptr, g_rx);
    cudaGetSymbolAddress((void**)&rwptr, g_rw);

    float* rq  = rxptr;
    float* rk  = rxptr + (size_t)MROWS * DMODEL;
    float* rv  = rxptr + 2 * (size_t)MROWS * DMODEL;
    float* rwq = rwptr;
    float* rwk = rwptr + (size_t)DMODEL * DMODEL;
    float* rwv = rwptr + 2 * (size_t)DMODEL * DMODEL;
    float* rwo = rwptr + 3 * (size_t)DMODEL * DMODEL;

    const int gemm_smem = G_SMEM_FLOATS * sizeof(float);   // 98304
    const int attn_smem = A_SMEM_FLOATS * sizeof(float);   // 110592
    cudaFuncSetAttribute(gemm_tf32, cudaFuncAttributeMaxDynamicSharedMemorySize, gemm_smem);
    cudaFuncSetAttribute(attn_kernel, cudaFuncAttributeMaxDynamicSharedMemorySize, attn_smem);

    // one fused pre-pass: 16-group k-permute + tf32-round all 7 GEMM operands
    PArgs pa;
    pa.in[0] = query; pa.out[0] = rq;  pa.n16[0] = MROWS * DMODEL / 16;
    pa.in[1] = key_;  pa.out[1] = rk;  pa.n16[1] = MROWS * DMODEL / 16;
    pa.in[2] = value; pa.out[2] = rv;  pa.n16[2] = MROWS * DMODEL / 16;
    pa.in[3] = Wq;    pa.out[3] = rwq; pa.n16[3] = DMODEL * DMODEL / 16;
    pa.in[4] = Wk;    pa.out[4] = rwk; pa.n16[4] = DMODEL * DMODEL / 16;
    pa.in[5] = Wv;    pa.out[5] = rwv; pa.n16[5] = DMODEL * DMODEL / 16;
    pa.in[6] = Wo;    pa.out[6] = rwo; pa.n16[6] = DMODEL * DMODEL / 16;
    dim3 pgrid((MROWS * DMODEL / 16 + 255) / 256, 7);
    permute_round<<<pgrid, 256>>>(pa);

    // fused QKV projections (grid.z selects matrix)
    GArgs qkv;
    qkv.X[0] = rq; qkv.W[0] = rwq; qkv.bias[0] = bq; qkv.Y[0] = qptr; qkv.mode[0] = 1;
    qkv.X[1] = rk; qkv.W[1] = rwk; qkv.bias[1] = bk; qkv.Y[1] = kptr; qkv.mode[1] = 3;
    qkv.X[2] = rv; qkv.W[2] = rwv; qkv.bias[2] = bv; qkv.Y[2] = vptr; qkv.mode[2] = 2;
    dim3 qkvgrid(DMODEL / 128, MROWS / 128, 3);   // (8, 32, 3)
    gemm_tf32<<<qkvgrid, 128, gemm_smem>>>(qkv);

    dim3 agrid(SEQ / 128, NHEADS, BATCH);         // (16, 16, 2)
    attn_kernel<<<agrid, 256, attn_smem>>>(qptr, kptr, vptr, aoptr);

    GArgs og;
    og.X[0] = aoptr; og.W[0] = rwo; og.bias[0] = bo; og.Y[0] = (float*)d_out; og.mode[0] = 0;
    og.X[1] = aoptr; og.W[1] = rwo; og.bias[1] = bo; og.Y[1] = (float*)d_out; og.mode[1] = 0;
    og.X[2] = aoptr; og.W[2] = rwo; og.bias[2] = bo; og.Y[2] = (float*)d_out; og.mode[2] = 0;
    dim3 ogrid(DMODEL / 128, MROWS / 128, 1);     // (8, 32, 1)
    gemm_tf32<<<ogrid, 128, gemm_smem>>>(og);
}